// round 11
// baseline (speedup 1.0000x reference)
#include <cuda_runtime.h>
#include <cuda_bf16.h>
#include <cuda_fp16.h>
#include <cstdint>

// Shapes (fixed): x [4,8,1024,512] -> M=32768 rows, K=512; W1,W2 [512,512].
#define MTOT  32768
#define MPERT 8192
#define KD    512
#define ND    512
#define NCHAN (MPERT * ND)
#define FLAG_CAP 1048576
#define MARGIN 4e-3f

// ---------------- scratch (no cudaMalloc allowed) ----------------
__device__ __align__(16) unsigned short g_xh[(size_t)MTOT * KD];   // x fp16
__device__ __align__(16) unsigned short g_w1h[KD * ND];            // W1 fp16
__device__ __align__(16) unsigned short g_w2h[KD * ND];            // W2 fp16
__device__ __align__(16) unsigned short g_s[(size_t)MTOT * ND];    // spikes fp16
__device__ int g_flags[FLAG_CAP];
__device__ int g_flag_count;

// ---------------- base-target PTX helpers (sm_80-era only) -----------------
__device__ __forceinline__ uint32_t smem_u32(const void* p) {
    uint32_t a;
    asm("{ .reg .u64 t; cvta.to.shared.u64 t, %1; cvt.u32.u64 %0, t; }"
        : "=r"(a) : "l"(p));
    return a;
}
__device__ __forceinline__ void cp_async16(uint32_t dst, const void* src) {
    asm volatile("cp.async.cg.shared.global [%0], [%1], 16;"
                 :: "r"(dst), "l"(src) : "memory");
}
__device__ __forceinline__ void cp_commit() {
    asm volatile("cp.async.commit_group;" ::: "memory");
}
template <int N>
__device__ __forceinline__ void cp_wait() {
    asm volatile("cp.async.wait_group %0;" :: "n"(N) : "memory");
}
__device__ __forceinline__ void ldsm_x4(uint32_t& r0, uint32_t& r1,
                                        uint32_t& r2, uint32_t& r3, uint32_t a) {
    asm volatile("ldmatrix.sync.aligned.m8n8.x4.shared.b16 {%0,%1,%2,%3}, [%4];"
                 : "=r"(r0), "=r"(r1), "=r"(r2), "=r"(r3) : "r"(a));
}
__device__ __forceinline__ void mma_fp16(float& c0, float& c1, float& c2, float& c3,
                                         uint32_t a0, uint32_t a1, uint32_t a2, uint32_t a3,
                                         uint32_t b0, uint32_t b1) {
    asm volatile(
        "mma.sync.aligned.m16n8k16.row.col.f32.f16.f16.f32 "
        "{%0,%1,%2,%3}, {%4,%5,%6,%7}, {%8,%9}, {%0,%1,%2,%3};"
        : "+f"(c0), "+f"(c1), "+f"(c2), "+f"(c3)
        : "r"(a0), "r"(a1), "r"(a2), "r"(a3), "r"(b0), "r"(b1));
}

// ============================================================================
// fp16 GEMM, CTA tile 64x128, 256 threads (8 warps, 2Mx4N @ 32x32 warp tiles),
// BK=64, stage = A 8KB + B 16KB = 24KB x3 (72KB) -> 3 CTA/SM = 24 warps/SM,
// grid (4, 512) = 2048 CTAs -> 4.61 waves (tail 8.5% vs 13.4% at 128x128).
// FUSED (GEMM1): t-interleaved M rows + LIF/flag epilogue writing fp16 spikes.
//   Fragment row r = wm*32 + mt*16 + k*8 + l4 -> t = (2mt+k)&3,
//   bn = tileM*16 + l4 + 8*wm;  h_t = acc[t>>1][nt][(t&1)*2+cc].
// Non-fused (GEMM2): plain fp32 C store.
// ============================================================================
#define STAGE_A 8192
#define STAGE   24576
#define SMEM_G  73728

template <bool FUSED>
__global__ void __launch_bounds__(256, 3) gemm_fp16_k(
    const unsigned short* __restrict__ A, const unsigned short* __restrict__ B,
    void* __restrict__ Cout)
{
    extern __shared__ char dynsmem[];
    const uint32_t sb = smem_u32(dynsmem);

    const int tid   = threadIdx.x;
    const int lane  = tid & 31;
    const int warp  = tid >> 5;            // 0..7
    const int wm    = warp >> 2;           // 0..1 (32 M rows)
    const int wn    = warp & 3;            // 0..3 (32 N cols)
    const int tileN = blockIdx.x;          // 0..3 (fast -> A L2 reuse)
    const int tileM = blockIdx.y;          // 0..511 (64 rows each)

    // global->smem load mapping
    const int aRow = tid >> 2;             // 0..63, 2 chunks each
    const int aC0  = (tid & 3) * 2;
    const int bRow = tid >> 1;             // 0..127, 4 chunks each
    const int bC0  = (tid & 1) * 4;
    const int lrow = lane & 15;
    const int lsel = lane >> 4;

    // A row (FUSED: t-interleaved within the 64-row tile)
    size_t arow;
    if (FUSED) {
        const int t_  = (aRow >> 3) & 3;
        const int bno = (aRow & 7) | ((aRow >> 5) << 3);   // 0..15
        arow = ((size_t)t_ * MPERT + tileM * 16 + bno) * KD;
    } else {
        arow = ((size_t)tileM * 64 + aRow) * KD;
    }
    const size_t brow = ((size_t)tileN * 128 + bRow) * KD;

    float acc[2][4][4];
    #pragma unroll
    for (int i = 0; i < 2; ++i)
        #pragma unroll
        for (int j = 0; j < 4; ++j)
            #pragma unroll
            for (int q = 0; q < 4; ++q) acc[i][j][q] = 0.f;

    auto load_stage = [&](int it) {
        const int k0 = it * 64;
        const uint32_t base = sb + (uint32_t)(it % 3) * STAGE;
        #pragma unroll
        for (int c = 0; c < 2; ++c) {
            uint32_t ch = (uint32_t)(aC0 + c);
            uint32_t sw = (ch ^ (uint32_t)(aRow & 7)) * 16u + (uint32_t)aRow * 128u;
            cp_async16(base + sw, A + arow + k0 + ch * 8);
        }
        #pragma unroll
        for (int c = 0; c < 4; ++c) {
            uint32_t ch = (uint32_t)(bC0 + c);
            uint32_t sw = (ch ^ (uint32_t)(bRow & 7)) * 16u + (uint32_t)bRow * 128u;
            cp_async16(base + STAGE_A + sw, B + brow + k0 + ch * 8);
        }
        cp_commit();
    };

    uint32_t a[2][4], b[4][2];

    auto load_a = [&](uint32_t ab, int ks) {
        #pragma unroll
        for (int mt = 0; mt < 2; ++mt) {
            int row = wm * 32 + mt * 16 + lrow;
            uint32_t ch = (uint32_t)(ks * 2 + lsel);
            uint32_t ad = ab + (uint32_t)row * 128u + ((ch ^ (uint32_t)(row & 7)) * 16u);
            ldsm_x4(a[mt][0], a[mt][1], a[mt][2], a[mt][3], ad);
        }
    };
    auto load_b = [&](uint32_t bb, int ks) {
        #pragma unroll
        for (int nt2 = 0; nt2 < 2; ++nt2) {
            int row = wn * 32 + nt2 * 16 + lrow;
            uint32_t ch = (uint32_t)(ks * 2 + lsel);
            uint32_t bd = bb + (uint32_t)row * 128u + ((ch ^ (uint32_t)(row & 7)) * 16u);
            uint32_t r0, r1, r2, r3;
            ldsm_x4(r0, r1, r2, r3, bd);
            b[nt2 * 2 + 0][0] = r0; b[nt2 * 2 + 1][0] = r1;
            b[nt2 * 2 + 0][1] = r2; b[nt2 * 2 + 1][1] = r3;
        }
    };

    load_stage(0);
    load_stage(1);

    for (int it = 0; it < 8; ++it) {
        if (it + 2 < 8) load_stage(it + 2);
        else cp_commit();
        cp_wait<2>();
        __syncthreads();

        const uint32_t base = sb + (uint32_t)(it % 3) * STAGE;

        #pragma unroll
        for (int ks = 0; ks < 4; ++ks) {
            load_a(base, ks);
            load_b(base + STAGE_A, ks);
            #pragma unroll
            for (int mt = 0; mt < 2; ++mt)
                #pragma unroll
                for (int nt = 0; nt < 4; ++nt)
                    mma_fp16(acc[mt][nt][0], acc[mt][nt][1],
                             acc[mt][nt][2], acc[mt][nt][3],
                             a[mt][0], a[mt][1], a[mt][2], a[mt][3],
                             b[nt][0], b[nt][1]);
        }
        __syncthreads();
    }
    cp_wait<0>();

    if constexpr (!FUSED) {
        float* __restrict__ C = (float*)Cout;
        const int rbase = tileM * 64 + wm * 32 + (lane >> 2);
        const int cbase = tileN * 128 + wn * 32 + (lane & 3) * 2;
        #pragma unroll
        for (int mt = 0; mt < 2; ++mt) {
            #pragma unroll
            for (int nt = 0; nt < 4; ++nt) {
                int r0 = rbase + mt * 16;
                int cc = cbase + nt * 8;
                *reinterpret_cast<float2*>(C + (size_t)r0 * ND + cc) =
                    make_float2(acc[mt][nt][0], acc[mt][nt][1]);
                *reinterpret_cast<float2*>(C + (size_t)(r0 + 8) * ND + cc) =
                    make_float2(acc[mt][nt][2], acc[mt][nt][3]);
            }
        }
    } else {
        // LIF + flags epilogue; fp16 spike = 0x3C00.
        unsigned short* __restrict__ s = (unsigned short*)Cout;
        const int bn = tileM * 16 + (lane >> 2) + 8 * wm;
        const int c0base = tileN * 128 + wn * 32 + (lane & 3) * 2;
        #pragma unroll
        for (int nt = 0; nt < 4; ++nt) {
            const int c0 = c0base + nt * 8;
            float v0 = 0.f, v1 = 0.f;
            bool r0 = false, r1 = false;
            uint32_t pk[4];
            #pragma unroll
            for (int t = 0; t < 4; ++t) {
                const int mt = t >> 1;
                const int q  = (t & 1) * 2;
                float h0 = acc[mt][nt][q + 0];
                float h1 = acc[mt][nt][q + 1];
                v0 = v0 + (h0 - v0) / 2.0f;
                v1 = v1 + (h1 - v1) / 2.0f;
                r0 |= (fabsf(v0 - 1.0f) < MARGIN);
                r1 |= (fabsf(v1 - 1.0f) < MARGIN);
                bool f0 = (v0 >= 1.0f), f1 = (v1 >= 1.0f);
                pk[t] = (f0 ? 0x3C00u : 0u) | ((f1 ? 0x3C00u : 0u) << 16);
                if (f0) v0 = 0.f;
                if (f1) v1 = 0.f;
            }
            #pragma unroll
            for (int t = 0; t < 4; ++t)
                *reinterpret_cast<uint32_t*>(
                    s + ((size_t)t * MPERT + bn) * ND + c0) = pk[t];
            if (r0) {
                int slot = atomicAdd(&g_flag_count, 1);
                if (slot < FLAG_CAP) g_flags[slot] = bn * ND + c0;
            }
            if (r1) {
                int slot = atomicAdd(&g_flag_count, 1);
                if (slot < FLAG_CAP) g_flags[slot] = bn * ND + c0 + 1;
            }
        }
    }
}

// ---------------- merged prep: fp32 -> fp16 for x, W1, W2 ------------------
#define NX4 (MTOT * KD / 4)
#define NW4 (KD * ND / 4)

__global__ void __launch_bounds__(256) prep_kernel(
    const float4* __restrict__ x, const float4* __restrict__ w1,
    const float4* __restrict__ w2, uint2* __restrict__ xh,
    uint2* __restrict__ w1h, uint2* __restrict__ w2h)
{
    if (blockIdx.x == 0 && threadIdx.x == 0) g_flag_count = 0;
    const int total = NX4 + 2 * NW4;
    const int stride = gridDim.x * blockDim.x;
    for (int i = blockIdx.x * blockDim.x + threadIdx.x; i < total; i += stride) {
        const float4* src;
        uint2* dst;
        int j;
        if (i < NX4)            { src = x;  dst = xh;  j = i; }
        else if (i < NX4 + NW4) { src = w1; dst = w1h; j = i - NX4; }
        else                    { src = w2; dst = w2h; j = i - NX4 - NW4; }
        float4 v = src[j];
        __half2 lo = __floats2half2_rn(v.x, v.y);
        __half2 hi = __floats2half2_rn(v.z, v.w);
        dst[j] = make_uint2(*reinterpret_cast<uint32_t*>(&lo),
                            *reinterpret_cast<uint32_t*>(&hi));
    }
}

// ============================================================================
// Fixup: warp-cooperative, bit-exact (round-9 kernel, proven).
// ============================================================================
#define FIX_WARPS 4

__global__ void __launch_bounds__(FIX_WARPS * 32) fixup_kernel(
    const float* __restrict__ x, const float* __restrict__ W1,
    unsigned short* __restrict__ s)
{
    __shared__ float sx[FIX_WARPS][4][KD];
    __shared__ float sw[FIX_WARPS][KD];

    const int warp = threadIdx.x >> 5;
    const int lane = threadIdx.x & 31;
    const int gw   = blockIdx.x * FIX_WARPS + warp;
    const int nw   = gridDim.x * FIX_WARPS;

    int count = g_flag_count;
    if (count > FLAG_CAP) count = FLAG_CAP;

    for (int j = gw; j < count; j += nw) {
        const int idx = g_flags[j];
        const int bn  = idx >> 9;
        const int c   = idx & 511;

        #pragma unroll
        for (int t = 0; t < 4; ++t) {
            const float4* xr = reinterpret_cast<const float4*>(
                x + ((size_t)t * MPERT + bn) * KD);
            #pragma unroll
            for (int i = 0; i < 4; ++i)
                reinterpret_cast<float4*>(sx[warp][t])[lane + i * 32] = xr[lane + i * 32];
        }
        const float4* wr = reinterpret_cast<const float4*>(W1 + (size_t)c * KD);
        #pragma unroll
        for (int i = 0; i < 4; ++i)
            reinterpret_cast<float4*>(sw[warp])[lane + i * 32] = wr[lane + i * 32];
        __syncwarp();

        float hq = 0.0f;
        if (lane < 4) {
            const float* xr = sx[warp][lane];
            const float* wr2 = sw[warp];
            float acc = 0.0f;
            #pragma unroll 8
            for (int k = 0; k < KD; ++k)
                acc = fmaf(xr[k], wr2[k], acc);
            hq = acc;
        }
        float h0 = __shfl_sync(0xffffffffu, hq, 0);
        float h1 = __shfl_sync(0xffffffffu, hq, 1);
        float h2 = __shfl_sync(0xffffffffu, hq, 2);
        float h3 = __shfl_sync(0xffffffffu, hq, 3);

        if (lane == 0) {
            float hh[4] = {h0, h1, h2, h3};
            float v = 0.0f;
            #pragma unroll
            for (int t = 0; t < 4; ++t) {
                v = v + (hh[t] - v) / 2.0f;
                bool fire = (v >= 1.0f);
                s[(size_t)t * NCHAN + idx] =
                    fire ? (unsigned short)0x3C00 : (unsigned short)0;
                if (fire) v = 0.0f;
            }
        }
        __syncwarp();
    }
}

// ---------------- launch ----------------
extern "C" void kernel_launch(void* const* d_in, const int* in_sizes, int n_in,
                              void* d_out, int out_size)
{
    const float* x  = (const float*)d_in[0];
    const float* W1 = (const float*)d_in[1];
    const float* W2 = (const float*)d_in[2];
    float* out = (float*)d_out;

    unsigned short *xh, *w1h, *w2h, *s;
    cudaGetSymbolAddress((void**)&xh,  g_xh);
    cudaGetSymbolAddress((void**)&w1h, g_w1h);
    cudaGetSymbolAddress((void**)&w2h, g_w2h);
    cudaGetSymbolAddress((void**)&s,   g_s);

    cudaFuncSetAttribute(gemm_fp16_k<true>,
                         cudaFuncAttributeMaxDynamicSharedMemorySize, SMEM_G);
    cudaFuncSetAttribute(gemm_fp16_k<false>,
                         cudaFuncAttributeMaxDynamicSharedMemorySize, SMEM_G);

    // merged conversions (also zeroes the flag counter)
    prep_kernel<<<2368, 256>>>((const float4*)x, (const float4*)W1,
                               (const float4*)W2, (uint2*)xh, (uint2*)w1h,
                               (uint2*)w2h);

    // GEMM1 fused: h = xh @ w1h^T (fp16), LIF + flags in epilogue
    gemm_fp16_k<true><<<dim3(4, 512), 256, SMEM_G>>>(xh, w1h, (void*)s);

    // exact fix-up of near-threshold channels (bit-identical to reference)
    fixup_kernel<<<592, FIX_WARPS * 32>>>(x, W1, s);

    // GEMM2: out = s @ w2h^T (fp16)
    gemm_fp16_k<false><<<dim3(4, 512), 256, SMEM_G>>>(s, w2h, (void*)out);
}

// round 12
// speedup vs baseline: 1.0675x; 1.0675x over previous
#include <cuda_runtime.h>
#include <cuda_bf16.h>
#include <cuda_fp16.h>
#include <cstdint>

// Shapes (fixed): x [4,8,1024,512] -> M=32768 rows, K=512; W1,W2 [512,512].
#define MTOT  32768
#define MPERT 8192
#define KD    512
#define ND    512
#define NCHAN (MPERT * ND)
#define FLAG_CAP 1048576
#define MARGIN 4e-3f

// ---------------- scratch (no cudaMalloc allowed) ----------------
__device__ __align__(16) unsigned short g_xh[(size_t)MTOT * KD];   // x fp16
__device__ __align__(16) unsigned short g_w1h[KD * ND];            // W1 fp16
__device__ __align__(16) unsigned short g_w2h[KD * ND];            // W2 fp16
__device__ __align__(16) unsigned short g_s[(size_t)MTOT * ND];    // spikes fp16
__device__ int g_flags[FLAG_CAP];
__device__ int g_flag_count;

// ---------------- base-target PTX helpers (sm_80-era only) -----------------
__device__ __forceinline__ uint32_t smem_u32(const void* p) {
    uint32_t a;
    asm("{ .reg .u64 t; cvta.to.shared.u64 t, %1; cvt.u32.u64 %0, t; }"
        : "=r"(a) : "l"(p));
    return a;
}
__device__ __forceinline__ void cp_async16(uint32_t dst, const void* src) {
    asm volatile("cp.async.cg.shared.global [%0], [%1], 16;"
                 :: "r"(dst), "l"(src) : "memory");
}
__device__ __forceinline__ void cp_commit() {
    asm volatile("cp.async.commit_group;" ::: "memory");
}
template <int N>
__device__ __forceinline__ void cp_wait() {
    asm volatile("cp.async.wait_group %0;" :: "n"(N) : "memory");
}
__device__ __forceinline__ void ldsm_x4(uint32_t& r0, uint32_t& r1,
                                        uint32_t& r2, uint32_t& r3, uint32_t a) {
    asm volatile("ldmatrix.sync.aligned.m8n8.x4.shared.b16 {%0,%1,%2,%3}, [%4];"
                 : "=r"(r0), "=r"(r1), "=r"(r2), "=r"(r3) : "r"(a));
}
__device__ __forceinline__ void mma_fp16(float& c0, float& c1, float& c2, float& c3,
                                         uint32_t a0, uint32_t a1, uint32_t a2, uint32_t a3,
                                         uint32_t b0, uint32_t b1) {
    asm volatile(
        "mma.sync.aligned.m16n8k16.row.col.f32.f16.f16.f32 "
        "{%0,%1,%2,%3}, {%4,%5,%6,%7}, {%8,%9}, {%0,%1,%2,%3};"
        : "+f"(c0), "+f"(c1), "+f"(c2), "+f"(c3)
        : "r"(a0), "r"(a1), "r"(a2), "r"(a3), "r"(b0), "r"(b1));
}

// ============================================================================
// fp16 GEMM (round-10 measured-best geometry, reverted from round-11):
// 512 threads (16 warps, 4x4 @ 32x32 warp tiles), CTA 128x128, BK=64,
// 32KB stage x3 (96KB) -> 2 CTA/SM = 32 warps/SM, grid (4,256).
// FUSED (GEMM1): t-interleaved M rows + LIF/flag epilogue writing fp16 spikes.
//   Fragment row r = wm*32 + mt*16 + k*8 + (lane>>2) -> t = 2mt+k,
//   bn = tileM*32 + (lane>>2) + 8*wm;  h_t = acc[t>>1][nt][(t&1)*2+cc].
// Non-fused (GEMM2): plain fp32 C store.
// ============================================================================
#define STAGE 32768
#define SMEM_G 98304

template <bool FUSED>
__global__ void __launch_bounds__(512, 2) gemm_fp16_k(
    const unsigned short* __restrict__ A, const unsigned short* __restrict__ B,
    void* __restrict__ Cout)
{
    extern __shared__ char dynsmem[];
    const uint32_t sb = smem_u32(dynsmem);

    const int tid   = threadIdx.x;
    const int lane  = tid & 31;
    const int warp  = tid >> 5;            // 0..15
    const int wm    = warp >> 2;           // 0..3 (32 M rows)
    const int wn    = warp & 3;            // 0..3 (32 N cols)
    const int tileN = blockIdx.x;          // 0..3 (fast -> A L2 reuse)
    const int tileM = blockIdx.y;          // 0..255

    const int ldRow = tid >> 2;            // 0..127
    const int ldC0  = (tid & 3) * 2;       // 2 chunks per tile per thread
    const int lrow  = lane & 15;
    const int lsel  = lane >> 4;

    // A row (FUSED: t-interleaved)
    size_t arow;
    if (FUSED) {
        const int t_  = (ldRow >> 3) & 3;
        const int bno = (ldRow & 7) | ((ldRow >> 5) << 3);
        arow = ((size_t)t_ * MPERT + tileM * 32 + bno) * KD;
    } else {
        arow = ((size_t)tileM * 128 + ldRow) * KD;
    }
    const size_t brow = ((size_t)tileN * 128 + ldRow) * KD;

    float acc[2][4][4];
    #pragma unroll
    for (int i = 0; i < 2; ++i)
        #pragma unroll
        for (int j = 0; j < 4; ++j)
            #pragma unroll
            for (int q = 0; q < 4; ++q) acc[i][j][q] = 0.f;

    auto load_stage = [&](int it) {
        const int k0 = it * 64;
        const uint32_t base  = sb + (uint32_t)(it % 3) * STAGE;
        const uint32_t swrow = (uint32_t)(ldRow & 7);
        #pragma unroll
        for (int c = 0; c < 2; ++c) {
            uint32_t ch = (uint32_t)(ldC0 + c);
            uint32_t sw = (ch ^ swrow) * 16u + (uint32_t)ldRow * 128u;
            cp_async16(base + sw,          A + arow + k0 + ch * 8);
            cp_async16(base + 16384 + sw,  B + brow + k0 + ch * 8);
        }
        cp_commit();
    };

    uint32_t a[2][4], b[4][2];

    auto load_a = [&](uint32_t ab, int ks) {
        #pragma unroll
        for (int mt = 0; mt < 2; ++mt) {
            int row = wm * 32 + mt * 16 + lrow;
            uint32_t ch = (uint32_t)(ks * 2 + lsel);
            uint32_t ad = ab + (uint32_t)row * 128u + ((ch ^ (uint32_t)(row & 7)) * 16u);
            ldsm_x4(a[mt][0], a[mt][1], a[mt][2], a[mt][3], ad);
        }
    };
    auto load_b = [&](uint32_t bb, int ks) {
        #pragma unroll
        for (int nt2 = 0; nt2 < 2; ++nt2) {
            int row = wn * 32 + nt2 * 16 + lrow;
            uint32_t ch = (uint32_t)(ks * 2 + lsel);
            uint32_t bd = bb + (uint32_t)row * 128u + ((ch ^ (uint32_t)(row & 7)) * 16u);
            uint32_t r0, r1, r2, r3;
            ldsm_x4(r0, r1, r2, r3, bd);
            b[nt2 * 2 + 0][0] = r0; b[nt2 * 2 + 1][0] = r1;
            b[nt2 * 2 + 0][1] = r2; b[nt2 * 2 + 1][1] = r3;
        }
    };

    load_stage(0);
    load_stage(1);

    for (int it = 0; it < 8; ++it) {
        if (it + 2 < 8) load_stage(it + 2);
        else cp_commit();
        cp_wait<2>();
        __syncthreads();

        const uint32_t base = sb + (uint32_t)(it % 3) * STAGE;

        #pragma unroll
        for (int ks = 0; ks < 4; ++ks) {
            load_a(base, ks);
            load_b(base + 16384, ks);
            #pragma unroll
            for (int mt = 0; mt < 2; ++mt)
                #pragma unroll
                for (int nt = 0; nt < 4; ++nt)
                    mma_fp16(acc[mt][nt][0], acc[mt][nt][1],
                             acc[mt][nt][2], acc[mt][nt][3],
                             a[mt][0], a[mt][1], a[mt][2], a[mt][3],
                             b[nt][0], b[nt][1]);
        }
        __syncthreads();
    }
    cp_wait<0>();

    if constexpr (!FUSED) {
        float* __restrict__ C = (float*)Cout;
        const int rbase = tileM * 128 + wm * 32 + (lane >> 2);
        const int cbase = tileN * 128 + wn * 32 + (lane & 3) * 2;
        #pragma unroll
        for (int mt = 0; mt < 2; ++mt) {
            #pragma unroll
            for (int nt = 0; nt < 4; ++nt) {
                int r0 = rbase + mt * 16;
                int cc = cbase + nt * 8;
                *reinterpret_cast<float2*>(C + (size_t)r0 * ND + cc) =
                    make_float2(acc[mt][nt][0], acc[mt][nt][1]);
                *reinterpret_cast<float2*>(C + (size_t)(r0 + 8) * ND + cc) =
                    make_float2(acc[mt][nt][2], acc[mt][nt][3]);
            }
        }
    } else {
        // LIF + flags epilogue (round-10 verified mapping); fp16 spike = 0x3C00.
        unsigned short* __restrict__ s = (unsigned short*)Cout;
        const int bn = tileM * 32 + (lane >> 2) + 8 * wm;
        const int c0base = tileN * 128 + wn * 32 + (lane & 3) * 2;
        #pragma unroll
        for (int nt = 0; nt < 4; ++nt) {
            const int c0 = c0base + nt * 8;
            float v0 = 0.f, v1 = 0.f;
            bool r0 = false, r1 = false;
            uint32_t pk[4];
            #pragma unroll
            for (int t = 0; t < 4; ++t) {
                const int mt = t >> 1;
                const int q  = (t & 1) * 2;
                float h0 = acc[mt][nt][q + 0];
                float h1 = acc[mt][nt][q + 1];
                v0 = v0 + (h0 - v0) / 2.0f;
                v1 = v1 + (h1 - v1) / 2.0f;
                r0 |= (fabsf(v0 - 1.0f) < MARGIN);
                r1 |= (fabsf(v1 - 1.0f) < MARGIN);
                bool f0 = (v0 >= 1.0f), f1 = (v1 >= 1.0f);
                pk[t] = (f0 ? 0x3C00u : 0u) | ((f1 ? 0x3C00u : 0u) << 16);
                if (f0) v0 = 0.f;
                if (f1) v1 = 0.f;
            }
            #pragma unroll
            for (int t = 0; t < 4; ++t)
                *reinterpret_cast<uint32_t*>(
                    s + ((size_t)t * MPERT + bn) * ND + c0) = pk[t];
            if (r0) {
                int slot = atomicAdd(&g_flag_count, 1);
                if (slot < FLAG_CAP) g_flags[slot] = bn * ND + c0;
            }
            if (r1) {
                int slot = atomicAdd(&g_flag_count, 1);
                if (slot < FLAG_CAP) g_flags[slot] = bn * ND + c0 + 1;
            }
        }
    }
}

// ---------------- merged prep: fp32 -> fp16 for x, W1, W2 ------------------
#define NX4 (MTOT * KD / 4)
#define NW4 (KD * ND / 4)

__global__ void __launch_bounds__(256) prep_kernel(
    const float4* __restrict__ x, const float4* __restrict__ w1,
    const float4* __restrict__ w2, uint2* __restrict__ xh,
    uint2* __restrict__ w1h, uint2* __restrict__ w2h)
{
    if (blockIdx.x == 0 && threadIdx.x == 0) g_flag_count = 0;
    const int total = NX4 + 2 * NW4;
    const int stride = gridDim.x * blockDim.x;
    for (int i = blockIdx.x * blockDim.x + threadIdx.x; i < total; i += stride) {
        const float4* src;
        uint2* dst;
        int j;
        if (i < NX4)            { src = x;  dst = xh;  j = i; }
        else if (i < NX4 + NW4) { src = w1; dst = w1h; j = i - NX4; }
        else                    { src = w2; dst = w2h; j = i - NX4 - NW4; }
        float4 v = src[j];
        __half2 lo = __floats2half2_rn(v.x, v.y);
        __half2 hi = __floats2half2_rn(v.z, v.w);
        dst[j] = make_uint2(*reinterpret_cast<uint32_t*>(&lo),
                            *reinterpret_cast<uint32_t*>(&hi));
    }
}

// ============================================================================
// Fixup: warp-cooperative, bit-exact (round-9 kernel, proven).
// ============================================================================
#define FIX_WARPS 4

__global__ void __launch_bounds__(FIX_WARPS * 32) fixup_kernel(
    const float* __restrict__ x, const float* __restrict__ W1,
    unsigned short* __restrict__ s)
{
    __shared__ float sx[FIX_WARPS][4][KD];
    __shared__ float sw[FIX_WARPS][KD];

    const int warp = threadIdx.x >> 5;
    const int lane = threadIdx.x & 31;
    const int gw   = blockIdx.x * FIX_WARPS + warp;
    const int nw   = gridDim.x * FIX_WARPS;

    int count = g_flag_count;
    if (count > FLAG_CAP) count = FLAG_CAP;

    for (int j = gw; j < count; j += nw) {
        const int idx = g_flags[j];
        const int bn  = idx >> 9;
        const int c   = idx & 511;

        #pragma unroll
        for (int t = 0; t < 4; ++t) {
            const float4* xr = reinterpret_cast<const float4*>(
                x + ((size_t)t * MPERT + bn) * KD);
            #pragma unroll
            for (int i = 0; i < 4; ++i)
                reinterpret_cast<float4*>(sx[warp][t])[lane + i * 32] = xr[lane + i * 32];
        }
        const float4* wr = reinterpret_cast<const float4*>(W1 + (size_t)c * KD);
        #pragma unroll
        for (int i = 0; i < 4; ++i)
            reinterpret_cast<float4*>(sw[warp])[lane + i * 32] = wr[lane + i * 32];
        __syncwarp();

        float hq = 0.0f;
        if (lane < 4) {
            const float* xr = sx[warp][lane];
            const float* wr2 = sw[warp];
            float acc = 0.0f;
            #pragma unroll 8
            for (int k = 0; k < KD; ++k)
                acc = fmaf(xr[k], wr2[k], acc);
            hq = acc;
        }
        float h0 = __shfl_sync(0xffffffffu, hq, 0);
        float h1 = __shfl_sync(0xffffffffu, hq, 1);
        float h2 = __shfl_sync(0xffffffffu, hq, 2);
        float h3 = __shfl_sync(0xffffffffu, hq, 3);

        if (lane == 0) {
            float hh[4] = {h0, h1, h2, h3};
            float v = 0.0f;
            #pragma unroll
            for (int t = 0; t < 4; ++t) {
                v = v + (hh[t] - v) / 2.0f;
                bool fire = (v >= 1.0f);
                s[(size_t)t * NCHAN + idx] =
                    fire ? (unsigned short)0x3C00 : (unsigned short)0;
                if (fire) v = 0.0f;
            }
        }
        __syncwarp();
    }
}

// ---------------- launch ----------------
extern "C" void kernel_launch(void* const* d_in, const int* in_sizes, int n_in,
                              void* d_out, int out_size)
{
    const float* x  = (const float*)d_in[0];
    const float* W1 = (const float*)d_in[1];
    const float* W2 = (const float*)d_in[2];
    float* out = (float*)d_out;

    unsigned short *xh, *w1h, *w2h, *s;
    cudaGetSymbolAddress((void**)&xh,  g_xh);
    cudaGetSymbolAddress((void**)&w1h, g_w1h);
    cudaGetSymbolAddress((void**)&w2h, g_w2h);
    cudaGetSymbolAddress((void**)&s,   g_s);

    cudaFuncSetAttribute(gemm_fp16_k<true>,
                         cudaFuncAttributeMaxDynamicSharedMemorySize, SMEM_G);
    cudaFuncSetAttribute(gemm_fp16_k<false>,
                         cudaFuncAttributeMaxDynamicSharedMemorySize, SMEM_G);

    // merged conversions (also zeroes the flag counter)
    prep_kernel<<<2368, 256>>>((const float4*)x, (const float4*)W1,
                               (const float4*)W2, (uint2*)xh, (uint2*)w1h,
                               (uint2*)w2h);

    // GEMM1 fused: h = xh @ w1h^T (fp16), LIF + flags in epilogue
    gemm_fp16_k<true><<<dim3(4, 256), 512, SMEM_G>>>(xh, w1h, (void*)s);

    // exact fix-up of near-threshold channels (bit-identical to reference)
    fixup_kernel<<<592, FIX_WARPS * 32>>>(x, W1, s);

    // GEMM2: out = s @ w2h^T (fp16)
    gemm_fp16_k<false><<<dim3(4, 256), 512, SMEM_G>>>(s, w2h, (void*)out);
}

// round 13
// speedup vs baseline: 1.0837x; 1.0152x over previous
#include <cuda_runtime.h>
#include <cuda_bf16.h>
#include <cuda_fp16.h>
#include <cstdint>

// Shapes (fixed): x [4,8,1024,512] -> M=32768 rows, K=512; W1,W2 [512,512].
#define MTOT  32768
#define MPERT 8192
#define KD    512
#define ND    512
#define NCHAN (MPERT * ND)
#define FLAG_CAP 1048576
#define MARGIN 4e-3f

// ---------------- scratch (no cudaMalloc allowed) ----------------
__device__ __align__(16) unsigned short g_xh[(size_t)MTOT * KD];   // x fp16
__device__ __align__(16) unsigned short g_w1h[KD * ND];            // W1 fp16
__device__ __align__(16) unsigned short g_w2h[KD * ND];            // W2 fp16
__device__ __align__(16) unsigned short g_s[(size_t)MTOT * ND];    // spikes fp16
__device__ int g_flags[FLAG_CAP];
__device__ int g_flag_count;

// ---------------- base-target PTX helpers (sm_80-era only) -----------------
__device__ __forceinline__ uint32_t smem_u32(const void* p) {
    uint32_t a;
    asm("{ .reg .u64 t; cvta.to.shared.u64 t, %1; cvt.u32.u64 %0, t; }"
        : "=r"(a) : "l"(p));
    return a;
}
__device__ __forceinline__ void cp_async16(uint32_t dst, const void* src) {
    asm volatile("cp.async.cg.shared.global [%0], [%1], 16;"
                 :: "r"(dst), "l"(src) : "memory");
}
__device__ __forceinline__ void cp_commit() {
    asm volatile("cp.async.commit_group;" ::: "memory");
}
template <int N>
__device__ __forceinline__ void cp_wait() {
    asm volatile("cp.async.wait_group %0;" :: "n"(N) : "memory");
}
__device__ __forceinline__ void ldsm_x4(uint32_t& r0, uint32_t& r1,
                                        uint32_t& r2, uint32_t& r3, uint32_t a) {
    asm volatile("ldmatrix.sync.aligned.m8n8.x4.shared.b16 {%0,%1,%2,%3}, [%4];"
                 : "=r"(r0), "=r"(r1), "=r"(r2), "=r"(r3) : "r"(a));
}
__device__ __forceinline__ void mma_fp16(float& c0, float& c1, float& c2, float& c3,
                                         uint32_t a0, uint32_t a1, uint32_t a2, uint32_t a3,
                                         uint32_t b0, uint32_t b1) {
    asm volatile(
        "mma.sync.aligned.m16n8k16.row.col.f32.f16.f16.f32 "
        "{%0,%1,%2,%3}, {%4,%5,%6,%7}, {%8,%9}, {%0,%1,%2,%3};"
        : "+f"(c0), "+f"(c1), "+f"(c2), "+f"(c3)
        : "r"(a0), "r"(a1), "r"(a2), "r"(a3), "r"(b0), "r"(b1));
}

// ============================================================================
// fp16 GEMM (round-12 proven geometry, byte-identical):
// 512 threads (16 warps, 4x4 @ 32x32 warp tiles), CTA 128x128, BK=64,
// 32KB stage x3 (96KB) -> 2 CTA/SM = 32 warps/SM, grid (4,256).
// FUSED (GEMM1): t-interleaved M rows + LIF/flag epilogue writing fp16 spikes.
// Non-fused (GEMM2): plain fp32 C store.
// ============================================================================
#define STAGE 32768
#define SMEM_G 98304

template <bool FUSED>
__global__ void __launch_bounds__(512, 2) gemm_fp16_k(
    const unsigned short* __restrict__ A, const unsigned short* __restrict__ B,
    void* __restrict__ Cout)
{
    extern __shared__ char dynsmem[];
    const uint32_t sb = smem_u32(dynsmem);

    const int tid   = threadIdx.x;
    const int lane  = tid & 31;
    const int warp  = tid >> 5;            // 0..15
    const int wm    = warp >> 2;           // 0..3 (32 M rows)
    const int wn    = warp & 3;            // 0..3 (32 N cols)
    const int tileN = blockIdx.x;          // 0..3 (fast -> A L2 reuse)
    const int tileM = blockIdx.y;          // 0..255

    const int ldRow = tid >> 2;            // 0..127
    const int ldC0  = (tid & 3) * 2;       // 2 chunks per tile per thread
    const int lrow  = lane & 15;
    const int lsel  = lane >> 4;

    // A row (FUSED: t-interleaved)
    size_t arow;
    if (FUSED) {
        const int t_  = (ldRow >> 3) & 3;
        const int bno = (ldRow & 7) | ((ldRow >> 5) << 3);
        arow = ((size_t)t_ * MPERT + tileM * 32 + bno) * KD;
    } else {
        arow = ((size_t)tileM * 128 + ldRow) * KD;
    }
    const size_t brow = ((size_t)tileN * 128 + ldRow) * KD;

    float acc[2][4][4];
    #pragma unroll
    for (int i = 0; i < 2; ++i)
        #pragma unroll
        for (int j = 0; j < 4; ++j)
            #pragma unroll
            for (int q = 0; q < 4; ++q) acc[i][j][q] = 0.f;

    auto load_stage = [&](int it) {
        const int k0 = it * 64;
        const uint32_t base  = sb + (uint32_t)(it % 3) * STAGE;
        const uint32_t swrow = (uint32_t)(ldRow & 7);
        #pragma unroll
        for (int c = 0; c < 2; ++c) {
            uint32_t ch = (uint32_t)(ldC0 + c);
            uint32_t sw = (ch ^ swrow) * 16u + (uint32_t)ldRow * 128u;
            cp_async16(base + sw,          A + arow + k0 + ch * 8);
            cp_async16(base + 16384 + sw,  B + brow + k0 + ch * 8);
        }
        cp_commit();
    };

    uint32_t a[2][4], b[4][2];

    auto load_a = [&](uint32_t ab, int ks) {
        #pragma unroll
        for (int mt = 0; mt < 2; ++mt) {
            int row = wm * 32 + mt * 16 + lrow;
            uint32_t ch = (uint32_t)(ks * 2 + lsel);
            uint32_t ad = ab + (uint32_t)row * 128u + ((ch ^ (uint32_t)(row & 7)) * 16u);
            ldsm_x4(a[mt][0], a[mt][1], a[mt][2], a[mt][3], ad);
        }
    };
    auto load_b = [&](uint32_t bb, int ks) {
        #pragma unroll
        for (int nt2 = 0; nt2 < 2; ++nt2) {
            int row = wn * 32 + nt2 * 16 + lrow;
            uint32_t ch = (uint32_t)(ks * 2 + lsel);
            uint32_t bd = bb + (uint32_t)row * 128u + ((ch ^ (uint32_t)(row & 7)) * 16u);
            uint32_t r0, r1, r2, r3;
            ldsm_x4(r0, r1, r2, r3, bd);
            b[nt2 * 2 + 0][0] = r0; b[nt2 * 2 + 1][0] = r1;
            b[nt2 * 2 + 0][1] = r2; b[nt2 * 2 + 1][1] = r3;
        }
    };

    load_stage(0);
    load_stage(1);

    for (int it = 0; it < 8; ++it) {
        if (it + 2 < 8) load_stage(it + 2);
        else cp_commit();
        cp_wait<2>();
        __syncthreads();

        const uint32_t base = sb + (uint32_t)(it % 3) * STAGE;

        #pragma unroll
        for (int ks = 0; ks < 4; ++ks) {
            load_a(base, ks);
            load_b(base + 16384, ks);
            #pragma unroll
            for (int mt = 0; mt < 2; ++mt)
                #pragma unroll
                for (int nt = 0; nt < 4; ++nt)
                    mma_fp16(acc[mt][nt][0], acc[mt][nt][1],
                             acc[mt][nt][2], acc[mt][nt][3],
                             a[mt][0], a[mt][1], a[mt][2], a[mt][3],
                             b[nt][0], b[nt][1]);
        }
        __syncthreads();
    }
    cp_wait<0>();

    if constexpr (!FUSED) {
        float* __restrict__ C = (float*)Cout;
        const int rbase = tileM * 128 + wm * 32 + (lane >> 2);
        const int cbase = tileN * 128 + wn * 32 + (lane & 3) * 2;
        #pragma unroll
        for (int mt = 0; mt < 2; ++mt) {
            #pragma unroll
            for (int nt = 0; nt < 4; ++nt) {
                int r0 = rbase + mt * 16;
                int cc = cbase + nt * 8;
                *reinterpret_cast<float2*>(C + (size_t)r0 * ND + cc) =
                    make_float2(acc[mt][nt][0], acc[mt][nt][1]);
                *reinterpret_cast<float2*>(C + (size_t)(r0 + 8) * ND + cc) =
                    make_float2(acc[mt][nt][2], acc[mt][nt][3]);
            }
        }
    } else {
        // LIF + flags epilogue (round-10 verified mapping); fp16 spike = 0x3C00.
        unsigned short* __restrict__ s = (unsigned short*)Cout;
        const int bn = tileM * 32 + (lane >> 2) + 8 * wm;
        const int c0base = tileN * 128 + wn * 32 + (lane & 3) * 2;
        #pragma unroll
        for (int nt = 0; nt < 4; ++nt) {
            const int c0 = c0base + nt * 8;
            float v0 = 0.f, v1 = 0.f;
            bool r0 = false, r1 = false;
            uint32_t pk[4];
            #pragma unroll
            for (int t = 0; t < 4; ++t) {
                const int mt = t >> 1;
                const int q  = (t & 1) * 2;
                float h0 = acc[mt][nt][q + 0];
                float h1 = acc[mt][nt][q + 1];
                v0 = v0 + (h0 - v0) / 2.0f;
                v1 = v1 + (h1 - v1) / 2.0f;
                r0 |= (fabsf(v0 - 1.0f) < MARGIN);
                r1 |= (fabsf(v1 - 1.0f) < MARGIN);
                bool f0 = (v0 >= 1.0f), f1 = (v1 >= 1.0f);
                pk[t] = (f0 ? 0x3C00u : 0u) | ((f1 ? 0x3C00u : 0u) << 16);
                if (f0) v0 = 0.f;
                if (f1) v1 = 0.f;
            }
            #pragma unroll
            for (int t = 0; t < 4; ++t)
                *reinterpret_cast<uint32_t*>(
                    s + ((size_t)t * MPERT + bn) * ND + c0) = pk[t];
            if (r0) {
                int slot = atomicAdd(&g_flag_count, 1);
                if (slot < FLAG_CAP) g_flags[slot] = bn * ND + c0;
            }
            if (r1) {
                int slot = atomicAdd(&g_flag_count, 1);
                if (slot < FLAG_CAP) g_flags[slot] = bn * ND + c0 + 1;
            }
        }
    }
}

// ============================================================================
// prep: fp32 -> fp16 for x, W1, W2 — block-partitioned, branchless inner loop.
// Blocks [0,2048): x (4 float4/thread); [2048,2112): W1 (2/thr);
// [2112,2176): W2 (2/thr). 512 threads.
// ============================================================================
#define NX4 (MTOT * KD / 4)
#define NW4 (KD * ND / 4)
#define PREP_XBLK 2048
#define PREP_WBLK 64
#define PREP_GRID (PREP_XBLK + 2 * PREP_WBLK)

__device__ __forceinline__ void cvt4(const float4* __restrict__ src,
                                     uint2* __restrict__ dst, int i) {
    float4 v = src[i];
    __half2 lo = __floats2half2_rn(v.x, v.y);
    __half2 hi = __floats2half2_rn(v.z, v.w);
    dst[i] = make_uint2(*reinterpret_cast<uint32_t*>(&lo),
                        *reinterpret_cast<uint32_t*>(&hi));
}

__global__ void __launch_bounds__(512) prep_kernel(
    const float4* __restrict__ x, const float4* __restrict__ w1,
    const float4* __restrict__ w2, uint2* __restrict__ xh,
    uint2* __restrict__ w1h, uint2* __restrict__ w2h)
{
    if (blockIdx.x == 0 && threadIdx.x == 0) g_flag_count = 0;
    const int b = blockIdx.x;
    if (b < PREP_XBLK) {
        // x: 4,194,304 float4 over 2048 blocks = 2048/block = 4/thread
        int base = b * 2048 + threadIdx.x;
        #pragma unroll
        for (int r = 0; r < 4; ++r)
            cvt4(x, xh, base + r * 512);
    } else if (b < PREP_XBLK + PREP_WBLK) {
        // W1: 65,536 float4 over 64 blocks = 1024/block = 2/thread
        int base = (b - PREP_XBLK) * 1024 + threadIdx.x;
        #pragma unroll
        for (int r = 0; r < 2; ++r)
            cvt4(w1, w1h, base + r * 512);
    } else {
        int base = (b - PREP_XBLK - PREP_WBLK) * 1024 + threadIdx.x;
        #pragma unroll
        for (int r = 0; r < 2; ++r)
            cvt4(w2, w2h, base + r * 512);
    }
}

// ============================================================================
// Fixup: warp-cooperative, bit-exact (round-9 kernel, proven).
// ============================================================================
#define FIX_WARPS 4

__global__ void __launch_bounds__(FIX_WARPS * 32) fixup_kernel(
    const float* __restrict__ x, const float* __restrict__ W1,
    unsigned short* __restrict__ s)
{
    __shared__ float sx[FIX_WARPS][4][KD];
    __shared__ float sw[FIX_WARPS][KD];

    const int warp = threadIdx.x >> 5;
    const int lane = threadIdx.x & 31;
    const int gw   = blockIdx.x * FIX_WARPS + warp;
    const int nw   = gridDim.x * FIX_WARPS;

    int count = g_flag_count;
    if (count > FLAG_CAP) count = FLAG_CAP;

    for (int j = gw; j < count; j += nw) {
        const int idx = g_flags[j];
        const int bn  = idx >> 9;
        const int c   = idx & 511;

        #pragma unroll
        for (int t = 0; t < 4; ++t) {
            const float4* xr = reinterpret_cast<const float4*>(
                x + ((size_t)t * MPERT + bn) * KD);
            #pragma unroll
            for (int i = 0; i < 4; ++i)
                reinterpret_cast<float4*>(sx[warp][t])[lane + i * 32] = xr[lane + i * 32];
        }
        const float4* wr = reinterpret_cast<const float4*>(W1 + (size_t)c * KD);
        #pragma unroll
        for (int i = 0; i < 4; ++i)
            reinterpret_cast<float4*>(sw[warp])[lane + i * 32] = wr[lane + i * 32];
        __syncwarp();

        float hq = 0.0f;
        if (lane < 4) {
            const float* xr = sx[warp][lane];
            const float* wr2 = sw[warp];
            float acc = 0.0f;
            #pragma unroll 8
            for (int k = 0; k < KD; ++k)
                acc = fmaf(xr[k], wr2[k], acc);
            hq = acc;
        }
        float h0 = __shfl_sync(0xffffffffu, hq, 0);
        float h1 = __shfl_sync(0xffffffffu, hq, 1);
        float h2 = __shfl_sync(0xffffffffu, hq, 2);
        float h3 = __shfl_sync(0xffffffffu, hq, 3);

        if (lane == 0) {
            float hh[4] = {h0, h1, h2, h3};
            float v = 0.0f;
            #pragma unroll
            for (int t = 0; t < 4; ++t) {
                v = v + (hh[t] - v) / 2.0f;
                bool fire = (v >= 1.0f);
                s[(size_t)t * NCHAN + idx] =
                    fire ? (unsigned short)0x3C00 : (unsigned short)0;
                if (fire) v = 0.0f;
            }
        }
        __syncwarp();
    }
}

// ---------------- launch ----------------
extern "C" void kernel_launch(void* const* d_in, const int* in_sizes, int n_in,
                              void* d_out, int out_size)
{
    const float* x  = (const float*)d_in[0];
    const float* W1 = (const float*)d_in[1];
    const float* W2 = (const float*)d_in[2];
    float* out = (float*)d_out;

    unsigned short *xh, *w1h, *w2h, *s;
    cudaGetSymbolAddress((void**)&xh,  g_xh);
    cudaGetSymbolAddress((void**)&w1h, g_w1h);
    cudaGetSymbolAddress((void**)&w2h, g_w2h);
    cudaGetSymbolAddress((void**)&s,   g_s);

    cudaFuncSetAttribute(gemm_fp16_k<true>,
                         cudaFuncAttributeMaxDynamicSharedMemorySize, SMEM_G);
    cudaFuncSetAttribute(gemm_fp16_k<false>,
                         cudaFuncAttributeMaxDynamicSharedMemorySize, SMEM_G);

    // merged conversions (also zeroes the flag counter)
    prep_kernel<<<PREP_GRID, 512>>>((const float4*)x, (const float4*)W1,
                                    (const float4*)W2, (uint2*)xh, (uint2*)w1h,
                                    (uint2*)w2h);

    // GEMM1 fused: h = xh @ w1h^T (fp16), LIF + flags in epilogue
    gemm_fp16_k<true><<<dim3(4, 256), 512, SMEM_G>>>(xh, w1h, (void*)s);

    // exact fix-up of near-threshold channels (bit-identical to reference)
    fixup_kernel<<<592, FIX_WARPS * 32>>>(x, W1, s);

    // GEMM2: out = s @ w2h^T (fp16)
    gemm_fp16_k<false><<<dim3(4, 256), 512, SMEM_G>>>(s, w2h, (void*)out);
}

// round 14
// speedup vs baseline: 1.1580x; 1.0686x over previous
#include <cuda_runtime.h>
#include <cuda_bf16.h>
#include <cuda_fp16.h>
#include <cstdint>

// Shapes (fixed): x [4,8,1024,512] -> M=32768 rows, K=512; W1,W2 [512,512].
#define MTOT  32768
#define MPERT 8192
#define KD    512
#define ND    512
#define NCHAN (MPERT * ND)
#define MARGIN 4e-3f

// ---------------- scratch (no cudaMalloc allowed) ----------------
__device__ __align__(16) unsigned short g_xh[(size_t)MTOT * KD];   // x fp16
__device__ __align__(16) unsigned short g_w1h[KD * ND];            // W1 fp16
__device__ __align__(16) unsigned short g_w2h[KD * ND];            // W2 fp16
__device__ __align__(16) unsigned short g_s[(size_t)MTOT * ND];    // spikes fp16
// per-bn 512-bit flag mask; zero-initialized, cleared by fixup after use
__device__ unsigned long long g_bnmask[MPERT][8];

// ---------------- base-target PTX helpers (sm_80-era only) -----------------
__device__ __forceinline__ uint32_t smem_u32(const void* p) {
    uint32_t a;
    asm("{ .reg .u64 t; cvta.to.shared.u64 t, %1; cvt.u32.u64 %0, t; }"
        : "=r"(a) : "l"(p));
    return a;
}
__device__ __forceinline__ void cp_async16(uint32_t dst, const void* src) {
    asm volatile("cp.async.cg.shared.global [%0], [%1], 16;"
                 :: "r"(dst), "l"(src) : "memory");
}
__device__ __forceinline__ void cp_commit() {
    asm volatile("cp.async.commit_group;" ::: "memory");
}
template <int N>
__device__ __forceinline__ void cp_wait() {
    asm volatile("cp.async.wait_group %0;" :: "n"(N) : "memory");
}
__device__ __forceinline__ void ldsm_x4(uint32_t& r0, uint32_t& r1,
                                        uint32_t& r2, uint32_t& r3, uint32_t a) {
    asm volatile("ldmatrix.sync.aligned.m8n8.x4.shared.b16 {%0,%1,%2,%3}, [%4];"
                 : "=r"(r0), "=r"(r1), "=r"(r2), "=r"(r3) : "r"(a));
}
__device__ __forceinline__ void mma_fp16(float& c0, float& c1, float& c2, float& c3,
                                         uint32_t a0, uint32_t a1, uint32_t a2, uint32_t a3,
                                         uint32_t b0, uint32_t b1) {
    asm volatile(
        "mma.sync.aligned.m16n8k16.row.col.f32.f16.f16.f32 "
        "{%0,%1,%2,%3}, {%4,%5,%6,%7}, {%8,%9}, {%0,%1,%2,%3};"
        : "+f"(c0), "+f"(c1), "+f"(c2), "+f"(c3)
        : "r"(a0), "r"(a1), "r"(a2), "r"(a3), "r"(b0), "r"(b1));
}

// ============================================================================
// fp16 GEMM (round-12/13 proven geometry, mainloop byte-identical):
// 512 threads (16 warps, 4x4 @ 32x32 warp tiles), CTA 128x128, BK=64,
// 32KB stage x3 (96KB) -> 2 CTA/SM = 32 warps/SM, grid (4,256).
// FUSED (GEMM1): t-interleaved M rows + LIF epilogue; flags -> bn bitmask.
// Non-fused (GEMM2): plain fp32 C store.
// ============================================================================
#define STAGE 32768
#define SMEM_G 98304

template <bool FUSED>
__global__ void __launch_bounds__(512, 2) gemm_fp16_k(
    const unsigned short* __restrict__ A, const unsigned short* __restrict__ B,
    void* __restrict__ Cout)
{
    extern __shared__ char dynsmem[];
    const uint32_t sb = smem_u32(dynsmem);

    const int tid   = threadIdx.x;
    const int lane  = tid & 31;
    const int warp  = tid >> 5;            // 0..15
    const int wm    = warp >> 2;           // 0..3 (32 M rows)
    const int wn    = warp & 3;            // 0..3 (32 N cols)
    const int tileN = blockIdx.x;          // 0..3 (fast -> A L2 reuse)
    const int tileM = blockIdx.y;          // 0..255

    const int ldRow = tid >> 2;            // 0..127
    const int ldC0  = (tid & 3) * 2;       // 2 chunks per tile per thread
    const int lrow  = lane & 15;
    const int lsel  = lane >> 4;

    // A row (FUSED: t-interleaved)
    size_t arow;
    if (FUSED) {
        const int t_  = (ldRow >> 3) & 3;
        const int bno = (ldRow & 7) | ((ldRow >> 5) << 3);
        arow = ((size_t)t_ * MPERT + tileM * 32 + bno) * KD;
    } else {
        arow = ((size_t)tileM * 128 + ldRow) * KD;
    }
    const size_t brow = ((size_t)tileN * 128 + ldRow) * KD;

    float acc[2][4][4];
    #pragma unroll
    for (int i = 0; i < 2; ++i)
        #pragma unroll
        for (int j = 0; j < 4; ++j)
            #pragma unroll
            for (int q = 0; q < 4; ++q) acc[i][j][q] = 0.f;

    auto load_stage = [&](int it) {
        const int k0 = it * 64;
        const uint32_t base  = sb + (uint32_t)(it % 3) * STAGE;
        const uint32_t swrow = (uint32_t)(ldRow & 7);
        #pragma unroll
        for (int c = 0; c < 2; ++c) {
            uint32_t ch = (uint32_t)(ldC0 + c);
            uint32_t sw = (ch ^ swrow) * 16u + (uint32_t)ldRow * 128u;
            cp_async16(base + sw,          A + arow + k0 + ch * 8);
            cp_async16(base + 16384 + sw,  B + brow + k0 + ch * 8);
        }
        cp_commit();
    };

    uint32_t a[2][4], b[4][2];

    auto load_a = [&](uint32_t ab, int ks) {
        #pragma unroll
        for (int mt = 0; mt < 2; ++mt) {
            int row = wm * 32 + mt * 16 + lrow;
            uint32_t ch = (uint32_t)(ks * 2 + lsel);
            uint32_t ad = ab + (uint32_t)row * 128u + ((ch ^ (uint32_t)(row & 7)) * 16u);
            ldsm_x4(a[mt][0], a[mt][1], a[mt][2], a[mt][3], ad);
        }
    };
    auto load_b = [&](uint32_t bb, int ks) {
        #pragma unroll
        for (int nt2 = 0; nt2 < 2; ++nt2) {
            int row = wn * 32 + nt2 * 16 + lrow;
            uint32_t ch = (uint32_t)(ks * 2 + lsel);
            uint32_t bd = bb + (uint32_t)row * 128u + ((ch ^ (uint32_t)(row & 7)) * 16u);
            uint32_t r0, r1, r2, r3;
            ldsm_x4(r0, r1, r2, r3, bd);
            b[nt2 * 2 + 0][0] = r0; b[nt2 * 2 + 1][0] = r1;
            b[nt2 * 2 + 0][1] = r2; b[nt2 * 2 + 1][1] = r3;
        }
    };

    load_stage(0);
    load_stage(1);

    for (int it = 0; it < 8; ++it) {
        if (it + 2 < 8) load_stage(it + 2);
        else cp_commit();
        cp_wait<2>();
        __syncthreads();

        const uint32_t base = sb + (uint32_t)(it % 3) * STAGE;

        #pragma unroll
        for (int ks = 0; ks < 4; ++ks) {
            load_a(base, ks);
            load_b(base + 16384, ks);
            #pragma unroll
            for (int mt = 0; mt < 2; ++mt)
                #pragma unroll
                for (int nt = 0; nt < 4; ++nt)
                    mma_fp16(acc[mt][nt][0], acc[mt][nt][1],
                             acc[mt][nt][2], acc[mt][nt][3],
                             a[mt][0], a[mt][1], a[mt][2], a[mt][3],
                             b[nt][0], b[nt][1]);
        }
        __syncthreads();
    }
    cp_wait<0>();

    if constexpr (!FUSED) {
        float* __restrict__ C = (float*)Cout;
        const int rbase = tileM * 128 + wm * 32 + (lane >> 2);
        const int cbase = tileN * 128 + wn * 32 + (lane & 3) * 2;
        #pragma unroll
        for (int mt = 0; mt < 2; ++mt) {
            #pragma unroll
            for (int nt = 0; nt < 4; ++nt) {
                int r0 = rbase + mt * 16;
                int cc = cbase + nt * 8;
                *reinterpret_cast<float2*>(C + (size_t)r0 * ND + cc) =
                    make_float2(acc[mt][nt][0], acc[mt][nt][1]);
                *reinterpret_cast<float2*>(C + (size_t)(r0 + 8) * ND + cc) =
                    make_float2(acc[mt][nt][2], acc[mt][nt][3]);
            }
        }
    } else {
        // LIF + flags epilogue; fp16 spike = 0x3C00; flags into bn bitmask.
        unsigned short* __restrict__ s = (unsigned short*)Cout;
        const int bn = tileM * 32 + (lane >> 2) + 8 * wm;
        const int c0base = tileN * 128 + wn * 32 + (lane & 3) * 2;
        #pragma unroll
        for (int nt = 0; nt < 4; ++nt) {
            const int c0 = c0base + nt * 8;          // even
            float v0 = 0.f, v1 = 0.f;
            bool r0 = false, r1 = false;
            uint32_t pk[4];
            #pragma unroll
            for (int t = 0; t < 4; ++t) {
                const int mt = t >> 1;
                const int q  = (t & 1) * 2;
                float h0 = acc[mt][nt][q + 0];
                float h1 = acc[mt][nt][q + 1];
                v0 = v0 + (h0 - v0) / 2.0f;
                v1 = v1 + (h1 - v1) / 2.0f;
                r0 |= (fabsf(v0 - 1.0f) < MARGIN);
                r1 |= (fabsf(v1 - 1.0f) < MARGIN);
                bool f0 = (v0 >= 1.0f), f1 = (v1 >= 1.0f);
                pk[t] = (f0 ? 0x3C00u : 0u) | ((f1 ? 0x3C00u : 0u) << 16);
                if (f0) v0 = 0.f;
                if (f1) v1 = 0.f;
            }
            #pragma unroll
            for (int t = 0; t < 4; ++t)
                *reinterpret_cast<uint32_t*>(
                    s + ((size_t)t * MPERT + bn) * ND + c0) = pk[t];
            if (r0 | r1) {
                // c0 even -> c0 and c0+1 share the same 64-bit word
                unsigned long long bits =
                    ((unsigned long long)(r0 ? 1u : 0u) << (c0 & 63)) |
                    ((unsigned long long)(r1 ? 1u : 0u) << ((c0 + 1) & 63));
                atomicOr(&g_bnmask[bn][c0 >> 6], bits);
            }
        }
    }
}

// ============================================================================
// prep: fp32 -> fp16 for x, W1, W2 — block-partitioned (round-13 proven).
// ============================================================================
#define PREP_XBLK 2048
#define PREP_WBLK 64
#define PREP_GRID (PREP_XBLK + 2 * PREP_WBLK)

__device__ __forceinline__ void cvt4(const float4* __restrict__ src,
                                     uint2* __restrict__ dst, int i) {
    float4 v = src[i];
    __half2 lo = __floats2half2_rn(v.x, v.y);
    __half2 hi = __floats2half2_rn(v.z, v.w);
    dst[i] = make_uint2(*reinterpret_cast<uint32_t*>(&lo),
                        *reinterpret_cast<uint32_t*>(&hi));
}

__global__ void __launch_bounds__(512) prep_kernel(
    const float4* __restrict__ x, const float4* __restrict__ w1,
    const float4* __restrict__ w2, uint2* __restrict__ xh,
    uint2* __restrict__ w1h, uint2* __restrict__ w2h)
{
    const int b = blockIdx.x;
    if (b < PREP_XBLK) {
        int base = b * 2048 + threadIdx.x;
        #pragma unroll
        for (int r = 0; r < 4; ++r)
            cvt4(x, xh, base + r * 512);
    } else if (b < PREP_XBLK + PREP_WBLK) {
        int base = (b - PREP_XBLK) * 1024 + threadIdx.x;
        #pragma unroll
        for (int r = 0; r < 2; ++r)
            cvt4(w1, w1h, base + r * 512);
    } else {
        int base = (b - PREP_XBLK - PREP_WBLK) * 1024 + threadIdx.x;
        #pragma unroll
        for (int r = 0; r < 2; ++r)
            cvt4(w2, w2h, base + r * 512);
    }
}

// ============================================================================
// Fixup v2: one warp per bn. Stage the 4 fp32 x rows ONCE per bn (smem),
// then process flagged channels 4 at a time: lanes {4f+t} each run the
// bit-exact sequential ascending-k single-accumulator 512-FMA chain for
// (flag f, timestep t); LIF on lane 4f via shuffles. Clears mask after use
// (graph-replay safe; statics start zero).
// smem per warp: sx[4][512] + sw[4][512] = 16KB; 4 warps/CTA -> 64KB dynamic.
// ============================================================================
#define FIX_SMEM 65536

__global__ void __launch_bounds__(128) fixup_kernel(
    const float* __restrict__ x, const float* __restrict__ W1,
    unsigned short* __restrict__ s)
{
    extern __shared__ float fsm[];
    const int warp = threadIdx.x >> 5;
    const int lane = threadIdx.x & 31;
    float* sx = fsm + warp * 4096;          // [4][512]
    float* sw = fsm + warp * 4096 + 2048;   // [4][512]

    const int bn = blockIdx.x * 4 + warp;   // 0..8191

    unsigned long long m[8];
    int total = 0;
    #pragma unroll
    for (int i = 0; i < 8; ++i) {
        m[i] = g_bnmask[bn][i];
        total += __popcll(m[i]);
    }
    if (total == 0) return;

    if (lane < 8) g_bnmask[bn][lane] = 0ull;   // clear for next replay

    // stage the 4 fp32 x rows (coalesced)
    #pragma unroll
    for (int t = 0; t < 4; ++t) {
        const float4* xr = reinterpret_cast<const float4*>(
            x + ((size_t)t * MPERT + bn) * KD);
        #pragma unroll
        for (int i = 0; i < 4; ++i)
            reinterpret_cast<float4*>(sx + t * 512)[lane + i * 32] = xr[lane + i * 32];
    }
    __syncwarp();

    while (total > 0) {
        // extract up to 4 set bits (identical on all lanes — uniform)
        int cs[4];
        int ng = 0;
        #pragma unroll
        for (int w8 = 0; w8 < 8; ++w8) {
            while (m[w8] && ng < 4) {
                int bpos = __ffsll((long long)m[w8]) - 1;
                cs[ng++] = w8 * 64 + bpos;
                m[w8] &= m[w8] - 1;
            }
        }
        total -= ng;

        // stage W1 rows for these channels (L2-resident; coalesced)
        for (int g = 0; g < ng; ++g) {
            const float4* wr = reinterpret_cast<const float4*>(
                W1 + (size_t)cs[g] * KD);
            #pragma unroll
            for (int i = 0; i < 4; ++i)
                reinterpret_cast<float4*>(sw + g * 512)[lane + i * 32] = wr[lane + i * 32];
        }
        __syncwarp();

        // bit-exact chains: lane = 4f + t
        const int f = lane >> 2;
        const int t = lane & 3;
        float hq = 0.0f;
        if (f < ng) {
            const float* xr = sx + t * 512;
            const float* wr = sw + f * 512;
            float acc = 0.0f;
            #pragma unroll 8
            for (int k = 0; k < KD; ++k)
                acc = fmaf(xr[k], wr[k], acc);
            hq = acc;
        }
        // gather the 4 timestep dots of this lane's flag group
        int gbase = lane & ~3;
        float h0 = __shfl_sync(0xffffffffu, hq, gbase + 0);
        float h1 = __shfl_sync(0xffffffffu, hq, gbase + 1);
        float h2 = __shfl_sync(0xffffffffu, hq, gbase + 2);
        float h3 = __shfl_sync(0xffffffffu, hq, gbase + 3);

        if (f < ng && t == 0) {
            const int idx = bn * ND + cs[f];
            float hh[4] = {h0, h1, h2, h3};
            float v = 0.0f;
            #pragma unroll
            for (int tt = 0; tt < 4; ++tt) {
                v = v + (hh[tt] - v) / 2.0f;
                bool fire = (v >= 1.0f);
                s[(size_t)tt * NCHAN + idx] =
                    fire ? (unsigned short)0x3C00 : (unsigned short)0;
                if (fire) v = 0.0f;
            }
        }
        __syncwarp();
    }
}

// ---------------- launch ----------------
extern "C" void kernel_launch(void* const* d_in, const int* in_sizes, int n_in,
                              void* d_out, int out_size)
{
    const float* x  = (const float*)d_in[0];
    const float* W1 = (const float*)d_in[1];
    const float* W2 = (const float*)d_in[2];
    float* out = (float*)d_out;

    unsigned short *xh, *w1h, *w2h, *s;
    cudaGetSymbolAddress((void**)&xh,  g_xh);
    cudaGetSymbolAddress((void**)&w1h, g_w1h);
    cudaGetSymbolAddress((void**)&w2h, g_w2h);
    cudaGetSymbolAddress((void**)&s,   g_s);

    cudaFuncSetAttribute(gemm_fp16_k<true>,
                         cudaFuncAttributeMaxDynamicSharedMemorySize, SMEM_G);
    cudaFuncSetAttribute(gemm_fp16_k<false>,
                         cudaFuncAttributeMaxDynamicSharedMemorySize, SMEM_G);
    cudaFuncSetAttribute(fixup_kernel,
                         cudaFuncAttributeMaxDynamicSharedMemorySize, FIX_SMEM);

    // conversions
    prep_kernel<<<PREP_GRID, 512>>>((const float4*)x, (const float4*)W1,
                                    (const float4*)W2, (uint2*)xh, (uint2*)w1h,
                                    (uint2*)w2h);

    // GEMM1 fused: h = xh @ w1h^T (fp16), LIF + bitmask flags in epilogue
    gemm_fp16_k<true><<<dim3(4, 256), 512, SMEM_G>>>(xh, w1h, (void*)s);

    // exact fix-up of near-threshold channels (bit-identical to reference)
    fixup_kernel<<<MPERT / 4, 128, FIX_SMEM>>>(x, W1, s);

    // GEMM2: out = s @ w2h^T (fp16)
    gemm_fp16_k<false><<<dim3(4, 256), 512, SMEM_G>>>(s, w2h, (void*)out);
}